// round 9
// baseline (speedup 1.0000x reference)
#include <cuda_runtime.h>
#include <cstdint>

// GraphRefiner: 256 graphs x (N=2000, F=2), shared sparse adjacency (E=7998).
// TAGConv(2->64,K=3) -> relu -> TAGConv(64->2,K=3) + residual.
// A (node-space) commutes with W (feature-space): layer-2 Horner'd in F=2 space.
// One CTA per graph, node state in SMEM, 2 CTAs/SM.
// R8: edge-balanced propagation (32 contiguous edges/thread, coalesced LDG.128
// records, branchless predicated flush, deterministic split-node fixup).

#define NNODES 2000
#define EMAX   8192
#define TPB    256
#define BTPB   1024
#define EPT    32          // edges per thread (EMAX / TPB)

typedef unsigned long long ull;

// per edge record: [0:16) src, [16:32) dst, [32:64) norm (f32 bits); canonical order
__device__ ull g_edge[EMAX];

// ======================= deterministic CSR build (1 block) ===================
__global__ void k_build(const int* __restrict__ row, const int* __restrict__ col,
                        const float* __restrict__ ew, int E) {
    extern __shared__ char bsm[];
    int*            hist = (int*)bsm;                       // 2048
    int*            rp   = hist + 2048;                     // 2048 (inclusive scan)
    float*          dinv = (float*)(rp + 2048);             // 2048
    unsigned short* ssrc = (unsigned short*)(dinv + 2048);  // 8192 u16
    float*          sew  = (float*)(ssrc + EMAX);           // 8192 f32

    int tid = threadIdx.x;
    int i0 = tid, i1 = tid + BTPB;

    hist[i0] = 0; hist[i1] = 0;
    __syncthreads();
    for (int e = tid; e < E; e += BTPB) atomicAdd(&hist[col[e]], 1);
    __syncthreads();

    rp[i0] = hist[i0]; rp[i1] = hist[i1];
    __syncthreads();
    for (int off = 1; off < 2048; off <<= 1) {
        int v0 = (i0 >= off) ? rp[i0 - off] : 0;
        int v1 = (i1 >= off) ? rp[i1 - off] : 0;
        __syncthreads();
        rp[i0] += v0; rp[i1] += v1;
        __syncthreads();
    }

    hist[i0] = i0 ? rp[i0 - 1] : 0;
    hist[i1] = rp[i1 - 1];
    __syncthreads();

    for (int e = tid; e < E; e += BTPB) {
        int c = col[e];
        int p = atomicAdd(&hist[c], 1);
        ssrc[p] = (unsigned short)row[e];
        sew[p]  = ew[e];
    }
    __syncthreads();

    // canonical per-node order (sort by (src, ew-bits)) -> bitwise determinism
    for (int n = tid; n < NNODES; n += BTPB) {
        int s = n ? rp[n - 1] : 0;
        int e = rp[n];
        for (int i = s + 1; i < e; ++i) {
            unsigned short ks = ssrc[i];
            float kw = sew[i];
            unsigned kb = __float_as_uint(kw);
            int j = i - 1;
            while (j >= s) {
                unsigned short js = ssrc[j];
                if (js > ks || (js == ks && __float_as_uint(sew[j]) > kb)) {
                    ssrc[j + 1] = js; sew[j + 1] = sew[j]; --j;
                } else break;
            }
            ssrc[j + 1] = ks; sew[j + 1] = kw;
        }
        float w = 0.f;
        for (int i = s; i < e; ++i) w += sew[i];
        dinv[n] = (w > 0.f) ? rsqrtf(w) : 0.f;
    }
    __syncthreads();

    // emit edge records (+ sentinel padding)
    for (int n = tid; n < NNODES; n += BTPB) {
        int s = n ? rp[n - 1] : 0;
        int e = rp[n];
        float di = dinv[n];
        for (int i = s; i < e; ++i) {
            float nm = di * sew[i] * dinv[ssrc[i]];
            unsigned meta = (unsigned)ssrc[i] | ((unsigned)n << 16);
            g_edge[i] = (ull)meta | ((ull)__float_as_uint(nm) << 32);
        }
    }
    for (int i = E + tid; i < EMAX; i += BTPB)
        g_edge[i] = (ull)(0xFFFFu << 16);        // dst = sentinel, norm = 0
}
#define BUILD_SMEM ((2048 + 2048 + 2048) * 4 + EMAX * 2 + EMAX * 4)

// ======================= main fused kernel ===================================

__device__ __forceinline__ ull pack2(float x, float y) {
    ull r; asm("mov.b64 %0, {%1, %2};" : "=l"(r) : "f"(x), "f"(y)); return r;
}
__device__ __forceinline__ void unpack2(ull v, float& x, float& y) {
    asm("mov.b64 {%0, %1}, %2;" : "=f"(x), "=f"(y) : "l"(v));
}
__device__ __forceinline__ void ffma2(ull& d, ull a, ull b) {
    asm("fma.rn.f32x2 %0, %1, %2, %0;" : "+l"(d) : "l"(a), "l"(b));
}
__device__ __forceinline__ ull add2(ull a, ull b) {
    ull r; asm("add.rn.f32x2 %0, %1, %2;" : "=l"(r) : "l"(a), "l"(b)); return r;
}
__device__ __forceinline__ unsigned smaddr(const void* p) {
    unsigned a;
    asm("{ .reg .u64 t; cvta.to.shared.u64 t, %1; cvt.u32.u64 %0, t; }" : "=r"(a) : "l"(p));
    return a;
}
// predicated 8B shared store (no BSSY divergence)
__device__ __forceinline__ void sts64_pred(int p, unsigned addr, ull v) {
    asm volatile("{ .reg .pred q; setp.ne.s32 q, %0, 0; @q st.shared.b64 [%1], %2; }"
                 :: "r"(p), "r"(addr), "l"(v));
}

// SMEM layout (bytes)
#define SM_BUF    0                        // 5 x ull[NNODES] = 80000
#define SM_WTS    (5 * NNODES * 8)         // 544 ull = 4352
#define SM_HA     (SM_WTS + 4352)          // ull[256]  head partial acc
#define SM_TA     (SM_HA + 2048)           // ull[256]  tail/owner partial acc
#define SM_HN     (SM_TA + 2048)           // short[256] head node (-1 none)
#define SM_ON     (SM_HN + 512)            // short[256] owner node (-1 none)
#define SM_TOTAL  (SM_ON + 512)            // 89472 -> 2 CTAs/SM

// edge-balanced propagation: Bdst[n] = sum_{edges->n} norm * Bsrc[src]
__device__ __forceinline__ void prop_eb(const ull* __restrict__ Bsrc,
                                        ull* __restrict__ Bdst,
                                        short* sm_hn, ull* sm_ha,
                                        short* sm_on, ull* sm_ta, int t) {
    unsigned dstA = smaddr(Bdst);
    const ulonglong2* ep = ((const ulonglong2*)g_edge) + t * (EPT / 2);

    int prevdst = -1;
    if (t > 0) prevdst = (int)(((unsigned)__ldg(&g_edge[t * EPT - 1])) >> 16);

    unsigned cur = 0xFFFFFFFFu;
    ull acc = 0;
    int first = 1, headPartial = 0;
    int myhead = -1; ull myheadacc = 0;

    #pragma unroll
    for (int q = 0; q < EPT / 2; ++q) {
        ulonglong2 rr = __ldg(&ep[q]);
        #pragma unroll
        for (int h = 0; h < 2; ++h) {
            ull rec = h ? rr.y : rr.x;
            unsigned meta = (unsigned)rec;
            unsigned d = meta >> 16;
            unsigned s = meta & 0xFFFFu;
            float w = __uint_as_float((unsigned)(rec >> 32));
            int change = (d != cur);
            int fl = change & (cur < NNODES);
            if (q == 0 && h == 0) headPartial = ((int)d == prevdst);
            int toHead = fl & first & headPartial;
            myhead    = toHead ? (int)cur : myhead;      // reg selects, no branch
            myheadacc = toHead ? acc : myheadacc;
            sts64_pred(fl & (toHead ^ 1), dstA + cur * 8u, acc);
            first = first & (fl ^ 1);
            acc = change ? 0ull : acc;
            cur = d;
            ffma2(acc, pack2(w, w), Bsrc[s]);
        }
    }

    // tail node of my range
    int ownnode = -1; ull ownacc = 0;
    if (cur < NNODES) {
        int tailSplit = 0;
        if (t < TPB - 1)
            tailSplit = ((((unsigned)__ldg(&g_edge[(t + 1) * EPT])) >> 16) == cur);
        if (first && headPartial)      { myhead = (int)cur; myheadacc = acc; }
        else if (tailSplit)            { ownnode = (int)cur; ownacc = acc; }
        else                           Bdst[cur] = acc;
    }
    sm_hn[t] = (short)myhead;  sm_ha[t] = myheadacc;
    sm_on[t] = (short)ownnode; sm_ta[t] = ownacc;
    __syncthreads();
    if (ownnode >= 0) {   // owner combines split-node partials in fixed order
        ull s2 = ownacc;
        for (int u = t + 1; u < TPB; ++u) {
            if ((int)sm_hn[u] != ownnode) break;
            s2 = add2(s2, sm_ha[u]);
        }
        Bdst[ownnode] = s2;
    }
    __syncthreads();
}

extern __shared__ char smem[];

__global__ void __launch_bounds__(TPB, 2) k6_main(
    const float* __restrict__ x,
    const float* __restrict__ W1, const float* __restrict__ b1,
    const float* __restrict__ W2, const float* __restrict__ b2,
    float* __restrict__ out)
{
    ull*   Bbase = (ull*)(smem + SM_BUF);
    ull*   wts   = (ull*)(smem + SM_WTS);
    ull*   sm_ha = (ull*)(smem + SM_HA);
    ull*   sm_ta = (ull*)(smem + SM_TA);
    short* sm_hn = (short*)(smem + SM_HN);
    short* sm_on = (short*)(smem + SM_ON);

    int tid = threadIdx.x;
    int g   = blockIdx.x;

    ull* B0  = Bbase;
    ull* B1v = B0 + NNODES;
    ull* B2v = B1v + NNODES;
    ull* B3v = B2v + NNODES;

    // ---- stage inputs ----
    const ulonglong2* xg2 = (const ulonglong2*)(x + (size_t)g * (2 * NNODES));
    ulonglong2* B02 = (ulonglong2*)B0;
    for (int i = tid; i < NNODES / 2; i += TPB) B02[i] = xg2[i];

    // weights packed per tile t (J=4): [w1t:16][w2t:16][b1t:2] = 34 ull
    {
        const ull* w1u = (const ull*)W1;
        const ull* w2u = (const ull*)W2;
        const ull* b1u = (const ull*)b1;
        for (int idx = tid; idx < 16 * 34; idx += TPB) {
            int t = idx / 34, r = idx % 34;
            ull v;
            if (r < 16)      { int i = r >> 1, d = r & 1; v = w1u[i * 32 + 2 * t + d]; }
            else if (r < 32) { int rr = r - 16; int j = rr >> 2, q = rr & 3; v = w2u[q * 64 + 4 * t + j]; }
            else             { v = b1u[2 * t + (r - 32)]; }
            wts[idx] = v;
        }
    }
    ull b2p = pack2(b2[0], b2[1]);
    __syncthreads();

    // phase schedule (nibble-packed): src {0,1,2,3,2,1}, dst {1,2,3,4,4,4},
    // add-into {-,-,-,2,1,0} (15 = none)
    const unsigned SPC = 0x123210u, DPC = 0x444321u, APC = 0x012FFFu;

    #pragma unroll 1
    for (int p = 0; p < 6; ++p) {
        if (p == 3) {
            // ---- dense phase: z in regs across tiles, w1/w2 phase-split ----
            #pragma unroll 1
            for (int strip = 0; strip < 2; ++strip) {
                int nb = tid + strip * 1024;
                ull z[16];
                #pragma unroll
                for (int m = 0; m < 4; ++m) {
                    int n = nb + (m << 8);
                    if (n >= NNODES) n = 0;
                    z[m * 4 + 0] = B0[n];  z[m * 4 + 1] = B1v[n];
                    z[m * 4 + 2] = B2v[n]; z[m * 4 + 3] = B3v[n];
                }
                ull y[16];
                #pragma unroll
                for (int c = 0; c < 16; ++c) y[c] = 0ull;

                #pragma unroll 1
                for (int t = 0; t < 16; ++t) {
                    const ulonglong2* wq = (const ulonglong2*)(wts + t * 34);
                    ull w[16], h[8];
                    #pragma unroll
                    for (int c = 0; c < 8; ++c) { ulonglong2 u = wq[c]; w[2*c] = u.x; w[2*c+1] = u.y; }
                    ulonglong2 ub = wq[16];
                    #pragma unroll
                    for (int m = 0; m < 4; ++m) {
                        ull h0 = ub.x, h1 = ub.y;
                        #pragma unroll
                        for (int r = 0; r < 4; ++r) {
                            float za, zb; unpack2(z[m * 4 + r], za, zb);
                            ull bza = pack2(za, za), bzb = pack2(zb, zb);
                            ffma2(h0, bza, w[(2 * r) * 2]);
                            ffma2(h1, bza, w[(2 * r) * 2 + 1]);
                            ffma2(h0, bzb, w[(2 * r + 1) * 2]);
                            ffma2(h1, bzb, w[(2 * r + 1) * 2 + 1]);
                        }
                        h[m * 2] = h0; h[m * 2 + 1] = h1;
                    }
                    #pragma unroll
                    for (int c = 0; c < 8; ++c) { ulonglong2 u = wq[8 + c]; w[2*c] = u.x; w[2*c+1] = u.y; }
                    #pragma unroll
                    for (int m = 0; m < 4; ++m) {
                        float ha, hb, hc, hd;
                        unpack2(h[m * 2], ha, hb); unpack2(h[m * 2 + 1], hc, hd);
                        ha = fmaxf(ha, 0.f); hb = fmaxf(hb, 0.f);
                        hc = fmaxf(hc, 0.f); hd = fmaxf(hd, 0.f);
                        ull d0 = pack2(ha, ha), d1 = pack2(hb, hb);
                        ull d2 = pack2(hc, hc), d3 = pack2(hd, hd);
                        #pragma unroll
                        for (int q2 = 0; q2 < 4; ++q2) {
                            ull acc = y[m * 4 + q2];
                            ffma2(acc, d0, w[q2]);
                            ffma2(acc, d1, w[4 + q2]);
                            ffma2(acc, d2, w[8 + q2]);
                            ffma2(acc, d3, w[12 + q2]);
                            y[m * 4 + q2] = acc;
                        }
                    }
                }
                #pragma unroll
                for (int m = 0; m < 4; ++m) {
                    int n = nb + (m << 8);
                    if (n < NNODES) {
                        B3v[n] = y[m * 4 + 3];
                        B2v[n] = y[m * 4 + 2];
                        B1v[n] = y[m * 4 + 1];
                        B0[n]  = add2(z[m * 4], add2(y[m * 4], b2p));
                    }
                }
            }
            __syncthreads();
        }

        int sp = (SPC >> (p * 4)) & 15;
        int dp = (DPC >> (p * 4)) & 15;
        prop_eb(Bbase + sp * NNODES, Bbase + dp * NNODES,
                sm_hn, sm_ha, sm_on, sm_ta, tid);

        int ap = (APC >> (p * 4)) & 15;
        if (ap != 15) {
            ulonglong2* d2 = (ulonglong2*)(Bbase + ap * NNODES);
            const ulonglong2* s2 = (const ulonglong2*)(Bbase + 4 * NNODES);
            for (int i = tid; i < NNODES / 2; i += TPB) {
                ulonglong2 u = d2[i], v = s2[i];
                u.x = add2(u.x, v.x); u.y = add2(u.y, v.y);
                d2[i] = u;
            }
            __syncthreads();
        }
    }

    ulonglong2* og2 = (ulonglong2*)(out + (size_t)g * (2 * NNODES));
    const ulonglong2* B0c = (const ulonglong2*)B0;
    for (int i = tid; i < NNODES / 2; i += TPB) og2[i] = B0c[i];
}

// ======================= host launch =========================================

extern "C" void kernel_launch(void* const* d_in, const int* in_sizes, int n_in,
                              void* d_out, int out_size) {
    const float* x   = (const float*)d_in[0];
    const int*   row = (const int*)d_in[1];
    const int*   col = (const int*)d_in[2];
    const float* ew  = (const float*)d_in[3];
    const float* W1  = (const float*)d_in[4];
    const float* b1  = (const float*)d_in[5];
    const float* W2  = (const float*)d_in[6];
    const float* b2  = (const float*)d_in[7];
    float* out = (float*)d_out;

    int E = in_sizes[1];
    int G = out_size / (2 * NNODES);

    cudaFuncSetAttribute(k_build, cudaFuncAttributeMaxDynamicSharedMemorySize, BUILD_SMEM);
    cudaFuncSetAttribute(k6_main, cudaFuncAttributeMaxDynamicSharedMemorySize, SM_TOTAL);

    k_build<<<1, BTPB, BUILD_SMEM>>>(row, col, ew, E);
    k6_main<<<G, TPB, SM_TOTAL>>>(x, W1, b1, W2, b2, out);
}

// round 10
// speedup vs baseline: 1.0746x; 1.0746x over previous
#include <cuda_runtime.h>
#include <cstdint>

// GraphRefiner: 256 graphs x (N=2000, F=2), shared sparse adjacency (E=7998).
// TAGConv(2->64,K=3) -> relu -> TAGConv(64->2,K=3) + residual.
// A (node-space) commutes with W (feature-space): layer-2 Horner'd in F=2 space.
// One CTA per graph, node state in SMEM, 2 CTAs/SM.
// R9: nodes processed in degree-sorted order (stable counting sort in k_build)
// -> warp lanes have equal degree -> no wasted edge-loop iterations; per-node
// meta packed u32 (start|deg|node); 4 independent accumulator chains.

#define NNODES 2000
#define EMAX   8192
#define TPB    256
#define BTPB   1024

typedef unsigned long long ull;

// ---- persistent device scratch ----
__device__ unsigned       g_meta[2048];     // per sorted position: start|deg<<13|node<<20
__device__ unsigned short g_ssrc16[EMAX];   // sorted-order edge sources
__device__ float          g_norm[EMAX];     // sorted-order edge norms

// ======================= deterministic build (1 block) =======================
__global__ void k_build(const int* __restrict__ row, const int* __restrict__ col,
                        const float* __restrict__ ew, int E) {
    extern __shared__ char bsm[];
    int*            hist  = (int*)bsm;                        // 2048
    int*            rp    = hist + 2048;                      // 2048 inclusive scan
    float*          dinv  = (float*)(rp + 2048);              // 2048
    unsigned short* ssrc  = (unsigned short*)(dinv + 2048);   // 8192 u16
    float*          sew   = (float*)(ssrc + 8192);            // 8192 f32
    int*            h2    = (int*)(sew + 8192);               // 8192 (128 deg x 64 grp)
    unsigned char*  degA  = (unsigned char*)(h2 + 8192);      // 2048
    unsigned char*  rankA = degA + 2048;                      // 2048
    unsigned short* pnode = (unsigned short*)(rankA + 2048);  // 2048
    int*            pd    = (int*)(pnode + 2048);             // 2048

    int tid = threadIdx.x;
    int i0 = tid, i1 = tid + BTPB;

    hist[i0] = 0; hist[i1] = 0;
    __syncthreads();
    for (int e = tid; e < E; e += BTPB) atomicAdd(&hist[col[e]], 1);
    __syncthreads();

    rp[i0] = hist[i0]; rp[i1] = hist[i1];
    __syncthreads();
    for (int off = 1; off < 2048; off <<= 1) {
        int v0 = (i0 >= off) ? rp[i0 - off] : 0;
        int v1 = (i1 >= off) ? rp[i1 - off] : 0;
        __syncthreads();
        rp[i0] += v0; rp[i1] += v1;
        __syncthreads();
    }

    hist[i0] = i0 ? rp[i0 - 1] : 0;
    hist[i1] = rp[i1 - 1];
    __syncthreads();

    for (int e = tid; e < E; e += BTPB) {
        int c = col[e];
        int p = atomicAdd(&hist[c], 1);
        ssrc[p] = (unsigned short)row[e];
        sew[p]  = ew[e];
    }
    __syncthreads();

    // canonical per-node order (sort by (src, ew-bits)) -> bitwise determinism
    for (int n = tid; n < NNODES; n += BTPB) {
        int s = n ? rp[n - 1] : 0;
        int e = rp[n];
        for (int i = s + 1; i < e; ++i) {
            unsigned short ks = ssrc[i];
            float kw = sew[i];
            unsigned kb = __float_as_uint(kw);
            int j = i - 1;
            while (j >= s) {
                unsigned short js = ssrc[j];
                if (js > ks || (js == ks && __float_as_uint(sew[j]) > kb)) {
                    ssrc[j + 1] = js; sew[j + 1] = sew[j]; --j;
                } else break;
            }
            ssrc[j + 1] = ks; sew[j + 1] = kw;
        }
        float w = 0.f;
        for (int i = s; i < e; ++i) w += sew[i];
        dinv[n] = (w > 0.f) ? rsqrtf(w) : 0.f;
        degA[n] = (unsigned char)(e - s);   // deg < 128 assumed (power-grid avg 4)
    }
    __syncthreads();

    // ---- stable counting sort of nodes by degree (ascending) ----
    for (int i = tid; i < 8192; i += BTPB) h2[i] = 0;
    __syncthreads();
    if (tid < 63) {                          // 63 groups of 32 contiguous nodes
        for (int i = 0; i < 32; ++i) {
            int n = tid * 32 + i;
            if (n < NNODES) {
                int d = degA[n];
                int idx = d * 64 + tid;
                rankA[n] = (unsigned char)h2[idx];
                h2[idx]  = h2[idx] + 1;
            }
        }
    }
    __syncthreads();
    // inclusive scan over 8192 (deg-major, group-minor)
    for (int off = 1; off < 8192; off <<= 1) {
        int v[8];
        #pragma unroll
        for (int k = 0; k < 8; ++k) { int i = tid + k * BTPB; v[k] = (i >= off) ? h2[i - off] : 0; }
        __syncthreads();
        #pragma unroll
        for (int k = 0; k < 8; ++k) { int i = tid + k * BTPB; h2[i] += v[k]; }
        __syncthreads();
    }
    // node -> sorted position
    for (int n = tid; n < NNODES; n += BTPB) {
        int d = degA[n], grp = n >> 5;
        int idx = d * 64 + grp;
        int pos = (idx ? h2[idx - 1] : 0) + (int)rankA[n];
        pnode[pos] = (unsigned short)n;
        pd[pos] = d;
    }
    for (int i = NNODES + tid; i < 2048; i += BTPB) pd[i] = 0;
    __syncthreads();
    // edge-start prefix over sorted positions
    for (int off = 1; off < 2048; off <<= 1) {
        int v0 = (i0 >= off) ? pd[i0 - off] : 0;
        int v1 = (i1 >= off) ? pd[i1 - off] : 0;
        __syncthreads();
        pd[i0] += v0; pd[i1] += v1;
        __syncthreads();
    }
    // emit sorted meta + edges
    for (int pos = tid; pos < NNODES; pos += BTPB) {
        int n = pnode[pos];
        int d = degA[n];
        int start = pd[pos] - d;
        g_meta[pos] = (unsigned)start | ((unsigned)d << 13) | ((unsigned)n << 20);
        int sc = n ? rp[n - 1] : 0;
        float di = dinv[n];
        for (int j = 0; j < d; ++j) {
            int ss = ssrc[sc + j];
            g_ssrc16[start + j] = (unsigned short)ss;
            g_norm[start + j]   = di * sew[sc + j] * dinv[ss];
        }
    }
}
#define BUILD_SMEM ((2048 + 2048 + 2048) * 4 + 8192 * 2 + 8192 * 4 + 8192 * 4 + 2048 + 2048 + 2048 * 2 + 2048 * 4)

// ======================= main fused kernel ===================================

__device__ __forceinline__ ull pack2(float x, float y) {
    ull r; asm("mov.b64 %0, {%1, %2};" : "=l"(r) : "f"(x), "f"(y)); return r;
}
__device__ __forceinline__ void unpack2(ull v, float& x, float& y) {
    asm("mov.b64 {%0, %1}, %2;" : "=f"(x), "=f"(y) : "l"(v));
}
__device__ __forceinline__ void ffma2(ull& d, ull a, ull b) {
    asm("fma.rn.f32x2 %0, %1, %2, %0;" : "+l"(d) : "l"(a), "l"(b));
}
__device__ __forceinline__ ull add2(ull a, ull b) {
    ull r; asm("add.rn.f32x2 %0, %1, %2;" : "=l"(r) : "l"(a), "l"(b)); return r;
}

// SMEM layout (bytes); 16B-aligned blocks
#define SM_BUF    0                        // 4 x ull[NNODES] = 64000
#define SM_WTS    (4 * NNODES * 8)         // 544 ull = 4352
#define SM_META   (SM_WTS + 4352)          // u32[2000] = 8000
#define SM_SRC    (SM_META + 8000)         // u16[8192] = 16384
#define SM_TOTAL  (SM_SRC + EMAX * 2)      // 92736 -> 2 CTAs/SM

__device__ __forceinline__ void propagate(const ull* __restrict__ src,
                                          ull* __restrict__ dst,
                                          const unsigned* __restrict__ meta,
                                          const unsigned short* __restrict__ ssrc,
                                          bool accum, int tid) {
    for (int pos = tid; pos < NNODES; pos += TPB) {
        unsigned mv = meta[pos];
        int st   = (int)(mv & 8191u);
        int deg  = (int)((mv >> 13) & 127u);
        int node = (int)(mv >> 20);
        ull a0 = 0, a1 = 0, a2 = 0, a3 = 0;
        int j = 0;
        for (; j + 4 <= deg; j += 4) {
            float w0 = __ldg(&g_norm[st + j]);
            float w1 = __ldg(&g_norm[st + j + 1]);
            float w2 = __ldg(&g_norm[st + j + 2]);
            float w3 = __ldg(&g_norm[st + j + 3]);
            ull v0 = src[ssrc[st + j]];
            ull v1 = src[ssrc[st + j + 1]];
            ull v2 = src[ssrc[st + j + 2]];
            ull v3 = src[ssrc[st + j + 3]];
            ffma2(a0, pack2(w0, w0), v0);
            ffma2(a1, pack2(w1, w1), v1);
            ffma2(a2, pack2(w2, w2), v2);
            ffma2(a3, pack2(w3, w3), v3);
        }
        if (j + 2 <= deg) {
            float w0 = __ldg(&g_norm[st + j]);
            float w1 = __ldg(&g_norm[st + j + 1]);
            ull v0 = src[ssrc[st + j]];
            ull v1 = src[ssrc[st + j + 1]];
            ffma2(a0, pack2(w0, w0), v0);
            ffma2(a1, pack2(w1, w1), v1);
            j += 2;
        }
        if (j < deg) {
            float w0 = __ldg(&g_norm[st + j]);
            ffma2(a2, pack2(w0, w0), src[ssrc[st + j]]);
        }
        if (accum) a0 = add2(a0, dst[node]);
        dst[node] = add2(add2(a0, a1), add2(a2, a3));
    }
}

extern __shared__ char smem[];

__global__ void __launch_bounds__(TPB, 2) k6_main(
    const float* __restrict__ x,
    const float* __restrict__ W1, const float* __restrict__ b1,
    const float* __restrict__ W2, const float* __restrict__ b2,
    float* __restrict__ out)
{
    ull* B0  = (ull*)(smem + SM_BUF);
    ull* B1v = B0 + NNODES;
    ull* B2v = B1v + NNODES;
    ull* B3v = B2v + NNODES;
    ull* wts = (ull*)(smem + SM_WTS);
    unsigned* meta = (unsigned*)(smem + SM_META);
    unsigned short* ssrc = (unsigned short*)(smem + SM_SRC);

    int tid = threadIdx.x;
    int g   = blockIdx.x;

    // ---- stage inputs ----
    const ulonglong2* xg2 = (const ulonglong2*)(x + (size_t)g * (2 * NNODES));
    ulonglong2* B02 = (ulonglong2*)B0;
    for (int i = tid; i < NNODES / 2; i += TPB) B02[i] = xg2[i];

    // weights packed per tile t (J=4): [w1t:16][w2t:16][b1t:2] = 34 ull
    {
        const ull* w1u = (const ull*)W1;
        const ull* w2u = (const ull*)W2;
        const ull* b1u = (const ull*)b1;
        for (int idx = tid; idx < 16 * 34; idx += TPB) {
            int t = idx / 34, r = idx % 34;
            ull v;
            if (r < 16)      { int i = r >> 1, d = r & 1; v = w1u[i * 32 + 2 * t + d]; }
            else if (r < 32) { int rr = r - 16; int j = rr >> 2, q = rr & 3; v = w2u[q * 64 + 4 * t + j]; }
            else             { v = b1u[2 * t + (r - 32)]; }
            wts[idx] = v;
        }
    }
    for (int i = tid; i < NNODES; i += TPB) meta[i] = g_meta[i];
    for (int i = tid; i < EMAX; i += TPB) ssrc[i] = g_ssrc16[i];
    ull b2p = pack2(b2[0], b2[1]);
    __syncthreads();

    // ---- layer-1 hops: z1..z3 ----
    propagate(B0,  B1v, meta, ssrc, false, tid); __syncthreads();
    propagate(B1v, B2v, meta, ssrc, false, tid); __syncthreads();
    propagate(B2v, B3v, meta, ssrc, false, tid); __syncthreads();

    // ---- dense phase: z in regs across tiles; w1/w2 phase-split ----
    #pragma unroll 1
    for (int strip = 0; strip < 2; ++strip) {
        int nb = tid + strip * 1024;
        ull z[16];
        #pragma unroll
        for (int m = 0; m < 4; ++m) {
            int n = nb + (m << 8);
            if (n >= NNODES) n = 0;              // dummy; write suppressed later
            z[m * 4 + 0] = B0[n];  z[m * 4 + 1] = B1v[n];
            z[m * 4 + 2] = B2v[n]; z[m * 4 + 3] = B3v[n];
        }
        ull y[16];
        #pragma unroll
        for (int c = 0; c < 16; ++c) y[c] = 0ull;

        #pragma unroll 1
        for (int t = 0; t < 16; ++t) {
            const ulonglong2* wq = (const ulonglong2*)(wts + t * 34);
            ull w[16], h[8];
            #pragma unroll
            for (int c = 0; c < 8; ++c) { ulonglong2 u = wq[c]; w[2*c] = u.x; w[2*c+1] = u.y; }
            ulonglong2 ub = wq[16];
            #pragma unroll
            for (int m = 0; m < 4; ++m) {
                ull h0 = ub.x, h1 = ub.y;
                #pragma unroll
                for (int r = 0; r < 4; ++r) {
                    float za, zb; unpack2(z[m * 4 + r], za, zb);
                    ull bza = pack2(za, za), bzb = pack2(zb, zb);
                    ffma2(h0, bza, w[(2 * r) * 2]);
                    ffma2(h1, bza, w[(2 * r) * 2 + 1]);
                    ffma2(h0, bzb, w[(2 * r + 1) * 2]);
                    ffma2(h1, bzb, w[(2 * r + 1) * 2 + 1]);
                }
                h[m * 2] = h0; h[m * 2 + 1] = h1;
            }
            #pragma unroll
            for (int c = 0; c < 8; ++c) { ulonglong2 u = wq[8 + c]; w[2*c] = u.x; w[2*c+1] = u.y; }
            #pragma unroll
            for (int m = 0; m < 4; ++m) {
                float ha, hb, hc, hd;
                unpack2(h[m * 2], ha, hb); unpack2(h[m * 2 + 1], hc, hd);
                ha = fmaxf(ha, 0.f); hb = fmaxf(hb, 0.f);
                hc = fmaxf(hc, 0.f); hd = fmaxf(hd, 0.f);
                ull d0 = pack2(ha, ha), d1 = pack2(hb, hb);
                ull d2 = pack2(hc, hc), d3 = pack2(hd, hd);
                #pragma unroll
                for (int q = 0; q < 4; ++q) {
                    ull acc = y[m * 4 + q];
                    ffma2(acc, d0, w[q]);
                    ffma2(acc, d1, w[4 + q]);
                    ffma2(acc, d2, w[8 + q]);
                    ffma2(acc, d3, w[12 + q]);
                    y[m * 4 + q] = acc;
                }
            }
        }
        #pragma unroll
        for (int m = 0; m < 4; ++m) {
            int n = nb + (m << 8);
            if (n < NNODES) {
                B3v[n] = y[m * 4 + 3];
                B2v[n] = y[m * 4 + 2];
                B1v[n] = y[m * 4 + 1];
                B0[n]  = add2(z[m * 4], add2(y[m * 4], b2p));
            }
        }
    }
    __syncthreads();

    // ---- layer-2 Horner: B2+=A*B3; B1+=A*B2; B0+=A*B1 ----
    propagate(B3v, B2v, meta, ssrc, true, tid); __syncthreads();
    propagate(B2v, B1v, meta, ssrc, true, tid); __syncthreads();
    propagate(B1v, B0,  meta, ssrc, true, tid); __syncthreads();

    ulonglong2* og2 = (ulonglong2*)(out + (size_t)g * (2 * NNODES));
    const ulonglong2* B0c = (const ulonglong2*)B0;
    for (int i = tid; i < NNODES / 2; i += TPB) og2[i] = B0c[i];
}

// ======================= host launch =========================================

extern "C" void kernel_launch(void* const* d_in, const int* in_sizes, int n_in,
                              void* d_out, int out_size) {
    const float* x   = (const float*)d_in[0];
    const int*   row = (const int*)d_in[1];
    const int*   col = (const int*)d_in[2];
    const float* ew  = (const float*)d_in[3];
    const float* W1  = (const float*)d_in[4];
    const float* b1  = (const float*)d_in[5];
    const float* W2  = (const float*)d_in[6];
    const float* b2  = (const float*)d_in[7];
    float* out = (float*)d_out;

    int E = in_sizes[1];
    int G = out_size / (2 * NNODES);

    cudaFuncSetAttribute(k_build, cudaFuncAttributeMaxDynamicSharedMemorySize, BUILD_SMEM);
    cudaFuncSetAttribute(k6_main, cudaFuncAttributeMaxDynamicSharedMemorySize, SM_TOTAL);

    k_build<<<1, BTPB, BUILD_SMEM>>>(row, col, ew, E);
    k6_main<<<G, TPB, SM_TOTAL>>>(x, W1, b1, W2, b2, out);
}

// round 12
// speedup vs baseline: 1.1087x; 1.0317x over previous
#include <cuda_runtime.h>
#include <cstdint>

// GraphRefiner: 256 graphs x (N=2000, F=2), shared sparse adjacency (E=7998).
// TAGConv(2->64,K=3) -> relu -> TAGConv(64->2,K=3) + residual.
// A (node-space) commutes with W (feature-space): layer-2 Horner'd in F=2 space.
// One CTA per graph, node state in SMEM, 2 CTAs/SM.
// R9: degree-sorted node processing (equal-degree warp lanes, packed meta).
// R10: k_build de-bloated -- positions need NOT be deterministic (only each
// node's own edge order matters for FP determinism), so rank-within-degree
// uses atomics and edge starts are closed-form from a single 128-bin scan.

#define NNODES 2000
#define EMAX   8192
#define TPB    256
#define BTPB   1024

typedef unsigned long long ull;

// ---- persistent device scratch ----
__device__ unsigned       g_meta[2048];     // per sorted position: start|deg<<13|node<<20
__device__ unsigned short g_ssrc16[EMAX];   // sorted-order edge sources
__device__ float          g_norm[EMAX];     // sorted-order edge norms

// ======================= build (1 block) =====================================
__global__ void k_build(const int* __restrict__ row, const int* __restrict__ col,
                        const float* __restrict__ ew, int E) {
    extern __shared__ char bsm[];
    int*            hist  = (int*)bsm;                        // 2048 (counts -> cursors)
    int*            rp    = hist + 2048;                      // 2048 inclusive rowptr
    float*          dinv  = (float*)(rp + 2048);              // 2048
    unsigned short* ssrc  = (unsigned short*)(dinv + 2048);   // 8192 u16
    float*          sew   = (float*)(ssrc + 8192);            // 8192 f32
    unsigned char*  degA  = (unsigned char*)(sew + 8192);     // 2048
    int*            degc  = (int*)(degA + 2048);              // 128 bin counts
    int*            nodestart = degc + 128;                   // 128
    int*            ebinstart = nodestart + 128;              // 128
    int*            degcur    = ebinstart + 128;              // 128
    int*            wsum      = degcur + 128;                 // 32

    int tid  = threadIdx.x;
    int lane = tid & 31;
    int wid  = tid >> 5;

    hist[tid] = 0; hist[tid + BTPB] = 0;
    if (tid < 128) { degc[tid] = 0; degcur[tid] = 0; }
    __syncthreads();

    for (int e = tid; e < E; e += BTPB) atomicAdd(&hist[col[e]], 1);
    __syncthreads();

    // ---- hierarchical inclusive scan of hist[2048] -> rp (3 barriers) ----
    {
        int a = hist[2 * tid], b = hist[2 * tid + 1];
        int s = a + b;
        #pragma unroll
        for (int off = 1; off < 32; off <<= 1) {
            int v = __shfl_up_sync(0xffffffffu, s, off);
            if (lane >= off) s += v;
        }
        if (lane == 31) wsum[wid] = s;
        __syncthreads();
        if (wid == 0) {
            int t = wsum[lane];
            #pragma unroll
            for (int off = 1; off < 32; off <<= 1) {
                int v = __shfl_up_sync(0xffffffffu, t, off);
                if (lane >= off) t += v;
            }
            wsum[lane] = t;
        }
        __syncthreads();
        int base = wid ? wsum[wid - 1] : 0;
        int incl = base + s;                // through element 2t+1
        rp[2 * tid]     = incl - b;
        rp[2 * tid + 1] = incl;
        __syncthreads();
        hist[2 * tid]     = incl - b - a;   // exclusive cursor
        hist[2 * tid + 1] = incl - b;
    }
    __syncthreads();

    // fill CSR slots (order nondeterministic; canonical sort below fixes values)
    for (int e = tid; e < E; e += BTPB) {
        int c = col[e];
        int p = atomicAdd(&hist[c], 1);
        ssrc[p] = (unsigned short)row[e];
        sew[p]  = ew[e];
    }
    __syncthreads();

    // canonical per-node order (sort by (src, ew-bits)) + dinv + degree
    for (int n = tid; n < NNODES; n += BTPB) {
        int s = n ? rp[n - 1] : 0;
        int e = rp[n];
        for (int i = s + 1; i < e; ++i) {
            unsigned short ks = ssrc[i];
            float kw = sew[i];
            unsigned kb = __float_as_uint(kw);
            int j = i - 1;
            while (j >= s) {
                unsigned short js = ssrc[j];
                if (js > ks || (js == ks && __float_as_uint(sew[j]) > kb)) {
                    ssrc[j + 1] = js; sew[j + 1] = sew[j]; --j;
                } else break;
            }
            ssrc[j + 1] = ks; sew[j + 1] = kw;
        }
        float w = 0.f;
        for (int i = s; i < e; ++i) w += sew[i];
        dinv[n] = (w > 0.f) ? rsqrtf(w) : 0.f;
        int d = e - s;
        degA[n] = (unsigned char)d;
        atomicAdd(&degc[d], 1);
    }
    __syncthreads();

    // 128-bin exclusive scans (node positions and edge starts) by warp 0
    if (wid == 0) {
        int c0 = degc[4 * lane], c1 = degc[4 * lane + 1];
        int c2 = degc[4 * lane + 2], c3 = degc[4 * lane + 3];
        int sn = c0 + c1 + c2 + c3;
        int se = c0 * (4 * lane) + c1 * (4 * lane + 1) + c2 * (4 * lane + 2) + c3 * (4 * lane + 3);
        int isn = sn, ise = se;
        #pragma unroll
        for (int off = 1; off < 32; off <<= 1) {
            int v0 = __shfl_up_sync(0xffffffffu, isn, off);
            int v1 = __shfl_up_sync(0xffffffffu, ise, off);
            if (lane >= off) { isn += v0; ise += v1; }
        }
        int bn = isn - sn, be = ise - se;   // exclusive bases for lane's 4 bins
        #pragma unroll
        for (int k = 0; k < 4; ++k) {
            int d = 4 * lane + k;
            int c = (k == 0) ? c0 : (k == 1) ? c1 : (k == 2) ? c2 : c3;
            nodestart[d] = bn;  ebinstart[d] = be;
            bn += c;            be += c * d;
        }
    }
    __syncthreads();

    // emit: position within degree bin via atomic (values stay deterministic)
    for (int n = tid; n < NNODES; n += BTPB) {
        int d = degA[n];
        int r = atomicAdd(&degcur[d], 1);
        int pos   = nodestart[d] + r;
        int start = ebinstart[d] + r * d;
        g_meta[pos] = (unsigned)start | ((unsigned)d << 13) | ((unsigned)n << 20);
        int sc = n ? rp[n - 1] : 0;
        float di = dinv[n];
        for (int j = 0; j < d; ++j) {
            int ss = ssrc[sc + j];
            g_ssrc16[start + j] = (unsigned short)ss;
            g_norm[start + j]   = di * sew[sc + j] * dinv[ss];
        }
    }
}
#define BUILD_SMEM ((2048 + 2048 + 2048) * 4 + 8192 * 2 + 8192 * 4 + 2048 + (128 * 4 + 32) * 4)

// ======================= main fused kernel ===================================

__device__ __forceinline__ ull pack2(float x, float y) {
    ull r; asm("mov.b64 %0, {%1, %2};" : "=l"(r) : "f"(x), "f"(y)); return r;
}
__device__ __forceinline__ void unpack2(ull v, float& x, float& y) {
    asm("mov.b64 {%0, %1}, %2;" : "=f"(x), "=f"(y) : "l"(v));
}
__device__ __forceinline__ void ffma2(ull& d, ull a, ull b) {
    asm("fma.rn.f32x2 %0, %1, %2, %0;" : "+l"(d) : "l"(a), "l"(b));
}
__device__ __forceinline__ ull add2(ull a, ull b) {
    ull r; asm("add.rn.f32x2 %0, %1, %2;" : "=l"(r) : "l"(a), "l"(b)); return r;
}

// SMEM layout (bytes); 16B-aligned blocks
#define SM_BUF    0                        // 4 x ull[NNODES] = 64000
#define SM_WTS    (4 * NNODES * 8)         // 544 ull = 4352
#define SM_META   (SM_WTS + 4352)          // u32[2000] = 8000
#define SM_SRC    (SM_META + 8000)         // u16[8192] = 16384
#define SM_TOTAL  (SM_SRC + EMAX * 2)      // 92736 -> 2 CTAs/SM

__device__ __forceinline__ void propagate(const ull* __restrict__ src,
                                          ull* __restrict__ dst,
                                          const unsigned* __restrict__ meta,
                                          const unsigned short* __restrict__ ssrc,
                                          bool accum, int tid) {
    for (int pos = tid; pos < NNODES; pos += TPB) {
        unsigned mv = meta[pos];
        int st   = (int)(mv & 8191u);
        int deg  = (int)((mv >> 13) & 127u);
        int node = (int)(mv >> 20);
        ull a0 = 0, a1 = 0, a2 = 0, a3 = 0;
        int j = 0;
        for (; j + 4 <= deg; j += 4) {
            float w0 = __ldg(&g_norm[st + j]);
            float w1 = __ldg(&g_norm[st + j + 1]);
            float w2 = __ldg(&g_norm[st + j + 2]);
            float w3 = __ldg(&g_norm[st + j + 3]);
            ull v0 = src[ssrc[st + j]];
            ull v1 = src[ssrc[st + j + 1]];
            ull v2 = src[ssrc[st + j + 2]];
            ull v3 = src[ssrc[st + j + 3]];
            ffma2(a0, pack2(w0, w0), v0);
            ffma2(a1, pack2(w1, w1), v1);
            ffma2(a2, pack2(w2, w2), v2);
            ffma2(a3, pack2(w3, w3), v3);
        }
        if (j + 2 <= deg) {
            float w0 = __ldg(&g_norm[st + j]);
            float w1 = __ldg(&g_norm[st + j + 1]);
            ull v0 = src[ssrc[st + j]];
            ull v1 = src[ssrc[st + j + 1]];
            ffma2(a0, pack2(w0, w0), v0);
            ffma2(a1, pack2(w1, w1), v1);
            j += 2;
        }
        if (j < deg) {
            float w0 = __ldg(&g_norm[st + j]);
            ffma2(a2, pack2(w0, w0), src[ssrc[st + j]]);
        }
        if (accum) a0 = add2(a0, dst[node]);
        dst[node] = add2(add2(a0, a1), add2(a2, a3));
    }
}

extern __shared__ char smem[];

__global__ void __launch_bounds__(TPB, 2) k6_main(
    const float* __restrict__ x,
    const float* __restrict__ W1, const float* __restrict__ b1,
    const float* __restrict__ W2, const float* __restrict__ b2,
    float* __restrict__ out)
{
    ull* B0  = (ull*)(smem + SM_BUF);
    ull* B1v = B0 + NNODES;
    ull* B2v = B1v + NNODES;
    ull* B3v = B2v + NNODES;
    ull* wts = (ull*)(smem + SM_WTS);
    unsigned* meta = (unsigned*)(smem + SM_META);
    unsigned short* ssrc = (unsigned short*)(smem + SM_SRC);

    int tid = threadIdx.x;
    int g   = blockIdx.x;

    // ---- stage inputs ----
    const ulonglong2* xg2 = (const ulonglong2*)(x + (size_t)g * (2 * NNODES));
    ulonglong2* B02 = (ulonglong2*)B0;
    for (int i = tid; i < NNODES / 2; i += TPB) B02[i] = xg2[i];

    // weights packed per tile t (J=4): [w1t:16][w2t:16][b1t:2] = 34 ull
    {
        const ull* w1u = (const ull*)W1;
        const ull* w2u = (const ull*)W2;
        const ull* b1u = (const ull*)b1;
        for (int idx = tid; idx < 16 * 34; idx += TPB) {
            int t = idx / 34, r = idx % 34;
            ull v;
            if (r < 16)      { int i = r >> 1, d = r & 1; v = w1u[i * 32 + 2 * t + d]; }
            else if (r < 32) { int rr = r - 16; int j = rr >> 2, q = rr & 3; v = w2u[q * 64 + 4 * t + j]; }
            else             { v = b1u[2 * t + (r - 32)]; }
            wts[idx] = v;
        }
    }
    for (int i = tid; i < NNODES; i += TPB) meta[i] = g_meta[i];
    {
        unsigned* s32 = (unsigned*)ssrc;
        const unsigned* g32 = (const unsigned*)g_ssrc16;
        for (int i = tid; i < EMAX / 2; i += TPB) s32[i] = g32[i];
    }
    ull b2p = pack2(b2[0], b2[1]);
    __syncthreads();

    // ---- layer-1 hops: z1..z3 ----
    propagate(B0,  B1v, meta, ssrc, false, tid); __syncthreads();
    propagate(B1v, B2v, meta, ssrc, false, tid); __syncthreads();
    propagate(B2v, B3v, meta, ssrc, false, tid); __syncthreads();

    // ---- dense phase: z in regs across tiles; w1/w2 phase-split ----
    #pragma unroll 1
    for (int strip = 0; strip < 2; ++strip) {
        int nb = tid + strip * 1024;
        ull z[16];
        #pragma unroll
        for (int m = 0; m < 4; ++m) {
            int n = nb + (m << 8);
            if (n >= NNODES) n = 0;              // dummy; write suppressed later
            z[m * 4 + 0] = B0[n];  z[m * 4 + 1] = B1v[n];
            z[m * 4 + 2] = B2v[n]; z[m * 4 + 3] = B3v[n];
        }
        ull y[16];
        #pragma unroll
        for (int c = 0; c < 16; ++c) y[c] = 0ull;

        #pragma unroll 1
        for (int t = 0; t < 16; ++t) {
            const ulonglong2* wq = (const ulonglong2*)(wts + t * 34);
            ull w[16], h[8];
            #pragma unroll
            for (int c = 0; c < 8; ++c) { ulonglong2 u = wq[c]; w[2*c] = u.x; w[2*c+1] = u.y; }
            ulonglong2 ub = wq[16];
            #pragma unroll
            for (int m = 0; m < 4; ++m) {
                ull h0 = ub.x, h1 = ub.y;
                #pragma unroll
                for (int r = 0; r < 4; ++r) {
                    float za, zb; unpack2(z[m * 4 + r], za, zb);
                    ull bza = pack2(za, za), bzb = pack2(zb, zb);
                    ffma2(h0, bza, w[(2 * r) * 2]);
                    ffma2(h1, bza, w[(2 * r) * 2 + 1]);
                    ffma2(h0, bzb, w[(2 * r + 1) * 2]);
                    ffma2(h1, bzb, w[(2 * r + 1) * 2 + 1]);
                }
                h[m * 2] = h0; h[m * 2 + 1] = h1;
            }
            #pragma unroll
            for (int c = 0; c < 8; ++c) { ulonglong2 u = wq[8 + c]; w[2*c] = u.x; w[2*c+1] = u.y; }
            #pragma unroll
            for (int m = 0; m < 4; ++m) {
                float ha, hb, hc, hd;
                unpack2(h[m * 2], ha, hb); unpack2(h[m * 2 + 1], hc, hd);
                ha = fmaxf(ha, 0.f); hb = fmaxf(hb, 0.f);
                hc = fmaxf(hc, 0.f); hd = fmaxf(hd, 0.f);
                ull d0 = pack2(ha, ha), d1 = pack2(hb, hb);
                ull d2 = pack2(hc, hc), d3 = pack2(hd, hd);
                #pragma unroll
                for (int q = 0; q < 4; ++q) {
                    ull acc = y[m * 4 + q];
                    ffma2(acc, d0, w[q]);
                    ffma2(acc, d1, w[4 + q]);
                    ffma2(acc, d2, w[8 + q]);
                    ffma2(acc, d3, w[12 + q]);
                    y[m * 4 + q] = acc;
                }
            }
        }
        #pragma unroll
        for (int m = 0; m < 4; ++m) {
            int n = nb + (m << 8);
            if (n < NNODES) {
                B3v[n] = y[m * 4 + 3];
                B2v[n] = y[m * 4 + 2];
                B1v[n] = y[m * 4 + 1];
                B0[n]  = add2(z[m * 4], add2(y[m * 4], b2p));
            }
        }
    }
    __syncthreads();

    // ---- layer-2 Horner: B2+=A*B3; B1+=A*B2; B0+=A*B1 ----
    propagate(B3v, B2v, meta, ssrc, true, tid); __syncthreads();
    propagate(B2v, B1v, meta, ssrc, true, tid); __syncthreads();
    propagate(B1v, B0,  meta, ssrc, true, tid); __syncthreads();

    ulonglong2* og2 = (ulonglong2*)(out + (size_t)g * (2 * NNODES));
    const ulonglong2* B0c = (const ulonglong2*)B0;
    for (int i = tid; i < NNODES / 2; i += TPB) og2[i] = B0c[i];
}

// ======================= host launch =========================================

extern "C" void kernel_launch(void* const* d_in, const int* in_sizes, int n_in,
                              void* d_out, int out_size) {
    const float* x   = (const float*)d_in[0];
    const int*   row = (const int*)d_in[1];
    const int*   col = (const int*)d_in[2];
    const float* ew  = (const float*)d_in[3];
    const float* W1  = (const float*)d_in[4];
    const float* b1  = (const float*)d_in[5];
    const float* W2  = (const float*)d_in[6];
    const float* b2  = (const float*)d_in[7];
    float* out = (float*)d_out;

    int E = in_sizes[1];
    int G = out_size / (2 * NNODES);

    cudaFuncSetAttribute(k_build, cudaFuncAttributeMaxDynamicSharedMemorySize, BUILD_SMEM);
    cudaFuncSetAttribute(k6_main, cudaFuncAttributeMaxDynamicSharedMemorySize, SM_TOTAL);

    k_build<<<1, BTPB, BUILD_SMEM>>>(row, col, ew, E);
    k6_main<<<G, TPB, SM_TOTAL>>>(x, W1, b1, W2, b2, out);
}